// round 1
// baseline (speedup 1.0000x reference)
#include <cuda_runtime.h>
#include <cuda_bf16.h>
#include <math.h>

// ---------------- problem-size constants (fixed for this dataset) -----------
#define MAXN   8192     // N = 6144
#define FDIM   128      // F
#define HDIM   64       // F/2
#define NBMAX  64       // NB = 48
#define MAXSEG 1024     // max atoms per molecule (expected ~128, 1024 = huge margin)
#define SPLIT  4        // blocks per segment in pair kernel

// ---------------- device scratch (no allocations allowed) -------------------
__device__ double g_energy;
__device__ float  g_q[MAXN];
__device__ float  g_sc6[MAXN];     // sqrt(softplus(c6_raw))
__device__ float  g_mu[MAXN * 3];
__device__ float  g_qsum[NBMAX];
__device__ int    g_cnt[NBMAX];
__device__ int    g_start[NBMAX];
__device__ int    g_end[NBMAX];

// ---------------- init ------------------------------------------------------
__global__ void init_kernel() {
    int t = threadIdx.x;
    if (t < NBMAX) {
        g_qsum[t]  = 0.0f;
        g_cnt[t]   = 0;
        g_start[t] = 0x7fffffff;
        g_end[t]   = 0;
    }
    if (t == 0) g_energy = 0.0;
}

// ---------------- per-atom features: q, sqrt(softplus(c6)), mu --------------
// one block (128 threads) per atom
__global__ void atom_features_kernel(
    const float* __restrict__ h0, const float* __restrict__ h1,
    const int*   __restrict__ batch,
    const float* __restrict__ qW1, const float* __restrict__ qb1,
    const float* __restrict__ qW2, const float* __restrict__ qb2,
    const float* __restrict__ cW1, const float* __restrict__ cb1,
    const float* __restrict__ cW2, const float* __restrict__ cb2,
    const float* __restrict__ muW, int N)
{
    int i = blockIdx.x;
    int t = threadIdx.x;             // 0..127

    __shared__ float h0row[FDIM];
    __shared__ float red[FDIM];

    h0row[t] = h0[i * FDIM + t];
    __syncthreads();

    // threads 0..63: q hidden unit t;  threads 64..127: c hidden unit t-64
    float val;
    if (t < HDIM) {
        float acc = qb1[t];
        #pragma unroll 8
        for (int f = 0; f < FDIM; f++) acc = fmaf(h0row[f], qW1[f * HDIM + t], acc);
        float s = acc / (1.0f + expf(-acc));       // silu
        val = s * qW2[t];
    } else {
        int k = t - HDIM;
        float acc = cb1[k];
        #pragma unroll 8
        for (int f = 0; f < FDIM; f++) acc = fmaf(h0row[f], cW1[f * HDIM + k], acc);
        float s = acc / (1.0f + expf(-acc));       // silu
        val = s * cW2[k];
    }
    red[t] = val;
    __syncthreads();

    // independent tree-reduce of each 64-wide half
    #pragma unroll
    for (int off = 32; off >= 1; off >>= 1) {
        if ((t & 63) < off) red[t] += red[t + off];
        __syncthreads();
    }

    if (t == 0) {
        float q_raw = red[0] + qb2[0];
        g_q[i] = q_raw;
        int b = batch[i];
        if (b >= 0 && b < NBMAX) {
            atomicAdd(&g_qsum[b], q_raw);
            atomicAdd(&g_cnt[b], 1);
            atomicMin(&g_start[b], i);
            atomicMax(&g_end[b], i + 1);
        }
        float c_raw = red[64] + cb2[0];
        // softplus, overflow-safe
        float sp = (c_raw > 20.0f) ? c_raw : log1pf(expf(c_raw));
        g_sc6[i] = sqrtf(sp);
    }
    __syncthreads();

    // mu[d] = sum_f h1[i,d,f] * muW[f]   (full-block reduction, 3x)
    float w = muW[t];
    #pragma unroll
    for (int d = 0; d < 3; d++) {
        red[t] = h1[(i * 3 + d) * FDIM + t] * w;
        __syncthreads();
        #pragma unroll
        for (int off = 64; off >= 1; off >>= 1) {
            if (t < off) red[t] += red[t + off];
            __syncthreads();
        }
        if (t == 0) g_mu[i * 3 + d] = red[0];
        __syncthreads();
    }
}

// ---------------- pairwise energy per molecule ------------------------------
__global__ void pair_energy_kernel(const float* __restrict__ pos)
{
    int b     = blockIdx.x / SPLIT;
    int slice = blockIdx.x % SPLIT;
    int s = g_start[b];
    int e = g_end[b];
    if (s >= e) return;
    int m = e - s;
    if (m > MAXSEG) m = MAXSEG;   // safety clamp (never hit for this data)

    __shared__ float sx[MAXSEG], sy[MAXSEG], sz[MAXSEG];
    __shared__ float sq[MAXSEG], sc[MAXSEG];
    __shared__ float smx[MAXSEG], smy[MAXSEG], smz[MAXSEG];

    float qmean = g_qsum[b] / fmaxf((float)g_cnt[b], 1.0f);

    for (int k = threadIdx.x; k < m; k += blockDim.x) {
        int i = s + k;
        sx[k] = pos[i * 3 + 0];
        sy[k] = pos[i * 3 + 1];
        sz[k] = pos[i * 3 + 2];
        sq[k] = g_q[i] - qmean;
        sc[k] = g_sc6[i];
        smx[k] = g_mu[i * 3 + 0];
        smy[k] = g_mu[i * 3 + 1];
        smz[k] = g_mu[i * 3 + 2];
    }
    __syncthreads();

    float acc = 0.0f;
    int total = m * m;
    for (int p = slice * blockDim.x + threadIdx.x; p < total; p += SPLIT * blockDim.x) {
        int i = p / m;
        int j = p - i * m;
        if (j <= i) continue;    // unordered pairs; all terms symmetric -> no 0.5

        float dx = sx[i] - sx[j];
        float dy = sy[i] - sy[j];
        float dz = sz[i] - sz[j];
        float d2 = dx * dx + dy * dy + dz * dz;
        float dist = sqrtf(d2 + 1e-8f);

        // Coulomb
        float f_taper = 1.0f - expf(-0.5f * dist);
        float ec = sq[i] * sq[j] / dist * f_taper;

        // vdW
        float r6 = d2 * d2 * d2;
        float ev = -(sc[i] * sc[j]) / (r6 + 20.0f);

        // dipole-dipole
        float mm  = smx[i] * smx[j] + smy[i] * smy[j] + smz[i] * smz[j];
        float mdi = smx[i] * dx + smy[i] * dy + smz[i] * dz;
        float mdj = smx[j] * dx + smy[j] * dy + smz[j] * dz;
        float invn = 1.0f / (dist + 1e-8f);
        float ed = (mm - 3.0f * mdi * mdj * invn * invn) / (d2 * dist + 10.0f);

        acc += ec * 14.399f + ev + ed;
    }

    // block reduce
    __shared__ float rbuf[256];
    int t = threadIdx.x;
    rbuf[t] = acc;
    __syncthreads();
    #pragma unroll
    for (int off = 128; off >= 1; off >>= 1) {
        if (t < off) rbuf[t] += rbuf[t + off];
        __syncthreads();
    }
    if (t == 0) atomicAdd(&g_energy, (double)rbuf[0]);
}

// ---------------- finalize --------------------------------------------------
__global__ void finalize_kernel(float* out) {
    out[0] = (float)g_energy;   // LONG_RANGE_SCALE = 1.0
}

// ---------------- launch ----------------------------------------------------
extern "C" void kernel_launch(void* const* d_in, const int* in_sizes, int n_in,
                              void* d_out, int out_size)
{
    const float* h0   = (const float*)d_in[0];
    const float* h1   = (const float*)d_in[1];
    const float* pos  = (const float*)d_in[2];
    const int*   batch= (const int*)  d_in[3];
    const float* qW1  = (const float*)d_in[4];
    const float* qb1  = (const float*)d_in[5];
    const float* qW2  = (const float*)d_in[6];
    const float* qb2  = (const float*)d_in[7];
    const float* cW1  = (const float*)d_in[8];
    const float* cb1  = (const float*)d_in[9];
    const float* cW2  = (const float*)d_in[10];
    const float* cb2  = (const float*)d_in[11];
    const float* muW  = (const float*)d_in[12];

    int N = in_sizes[3];   // batch has N elements

    init_kernel<<<1, NBMAX>>>();
    atom_features_kernel<<<N, FDIM>>>(h0, h1, batch,
                                      qW1, qb1, qW2, qb2,
                                      cW1, cb1, cW2, cb2, muW, N);
    pair_energy_kernel<<<NBMAX * SPLIT, 256>>>(pos);
    finalize_kernel<<<1, 1>>>((float*)d_out);
}

// round 2
// speedup vs baseline: 1.0179x; 1.0179x over previous
#include <cuda_runtime.h>
#include <cuda_bf16.h>
#include <math.h>

#define MAXN   8192
#define FDIM   128
#define HDIM   64
#define NB     48
#define TA     32        // atoms per feature block
#define MAXSEG 1024      // max atoms per molecule (expected ~128)
#define SPLIT  8         // blocks per molecule in pair kernel

// ---------------- device scratch ----------------
__device__ double g_energy;
__device__ int    g_done;
__device__ float  g_q[MAXN];
__device__ float  g_sc6[MAXN];      // sqrt(softplus(c6_raw))
__device__ float  g_mu[MAXN * 3];

// ================= features: q, sqrt(softplus(c6)), mu =================
// 256 threads, 32 atoms per block.
// Threads 0..255: hu_full = t&127 (0-63 -> q MLP, 64-127 -> c MLP), slice = t>>7.
__global__ __launch_bounds__(256) void features_kernel(
    const float* __restrict__ h0, const float* __restrict__ h1,
    const float* __restrict__ qW1, const float* __restrict__ qb1,
    const float* __restrict__ qW2, const float* __restrict__ qb2,
    const float* __restrict__ cW1, const float* __restrict__ cb1,
    const float* __restrict__ cW2, const float* __restrict__ cb2,
    const float* __restrict__ muW)
{
    int t  = threadIdx.x;
    int a0 = blockIdx.x * TA;

    if (blockIdx.x == 0 && t == 0) { g_energy = 0.0; g_done = 0; }

    __shared__ float h0s[TA][FDIM];      // 16 KB
    __shared__ float red[128 * 33];      // padded stride 33 -> ~16.9 KB

    // stage h0 tile (coalesced float4)
    {
        const float4* src = (const float4*)(h0 + (size_t)a0 * FDIM);
        float4* dst = (float4*)&h0s[0][0];
        #pragma unroll
        for (int k = t; k < TA * FDIM / 4; k += 256) dst[k] = src[k];
    }
    __syncthreads();

    int hu_full = t & 127;
    int mlp     = hu_full >> 6;          // 0 = q, 1 = c
    int hu      = hu_full & 63;
    int slice   = t >> 7;                // 0 or 1: which 16 atoms
    int abase   = slice * 16;

    const float* W1 = mlp ? cW1 : qW1;
    const float* B1 = mlp ? cb1 : qb1;
    const float* W2 = mlp ? cW2 : qW2;

    float acc[16];
    #pragma unroll
    for (int a = 0; a < 16; a++) acc[a] = 0.0f;

    #pragma unroll 4
    for (int f0 = 0; f0 < FDIM; f0 += 4) {
        float w0 = W1[(f0 + 0) * HDIM + hu];
        float w1 = W1[(f0 + 1) * HDIM + hu];
        float w2 = W1[(f0 + 2) * HDIM + hu];
        float w3 = W1[(f0 + 3) * HDIM + hu];
        #pragma unroll
        for (int a = 0; a < 16; a++) {
            float4 h = *(const float4*)&h0s[abase + a][f0];  // broadcast within warp
            acc[a] = fmaf(h.x, w0, acc[a]);
            acc[a] = fmaf(h.y, w1, acc[a]);
            acc[a] = fmaf(h.z, w2, acc[a]);
            acc[a] = fmaf(h.w, w3, acc[a]);
        }
    }

    float b1v = B1[hu];
    float w2v = W2[hu];
    #pragma unroll
    for (int a = 0; a < 16; a++) {
        float pre = acc[a] + b1v;
        float s   = pre / (1.0f + __expf(-pre));   // silu
        red[hu_full * 33 + abase + a] = s * w2v;   // conflict-free (stride 33)
    }
    __syncthreads();

    // reduce over 64 hidden units: 64 outputs = 2 mlps x 32 atoms
    if (t < 64) {
        int mlp2 = t >> 5;
        int a    = t & 31;
        float sum = 0.0f;
        #pragma unroll 8
        for (int h = 0; h < HDIM; h++)
            sum += red[(mlp2 * 64 + h) * 33 + a];
        if (mlp2 == 0) {
            g_q[a0 + a] = sum + qb2[0];
        } else {
            float c_raw = sum + cb2[0];
            float sp = (c_raw > 20.0f) ? c_raw : log1pf(__expf(c_raw));
            g_sc6[a0 + a] = sqrtf(sp);
        }
    }

    // mu[d] = h1[i,d,:] . muW  -- warp per row, 96 rows, 8 warps -> 12 rows each
    int warp = t >> 5, lane = t & 31;
    float mw0 = muW[lane], mw1 = muW[lane + 32], mw2 = muW[lane + 64], mw3 = muW[lane + 96];
    for (int r = warp; r < 3 * TA; r += 8) {
        int atom = a0 + r / 3, d = r % 3;
        const float* row = h1 + ((size_t)atom * 3 + d) * FDIM;
        float v = row[lane] * mw0 + row[lane + 32] * mw1
                + row[lane + 64] * mw2 + row[lane + 96] * mw3;
        #pragma unroll
        for (int off = 16; off >= 1; off >>= 1)
            v += __shfl_xor_sync(0xffffffffu, v, off);
        if (lane == 0) g_mu[atom * 3 + d] = v;
    }
}

// ================= pairwise energy, one molecule per SPLIT blocks =================
__global__ __launch_bounds__(256) void pair_kernel(
    const float* __restrict__ pos, const int* __restrict__ batch,
    float* __restrict__ out, int N)
{
    int b     = blockIdx.x / SPLIT;
    int slice = blockIdx.x % SPLIT;
    int t     = threadIdx.x;

    __shared__ int   s_s, s_e;
    __shared__ float sx[MAXSEG], sy[MAXSEG], sz[MAXSEG];
    __shared__ float sq[MAXSEG], sc[MAXSEG];
    __shared__ float smx[MAXSEG], smy[MAXSEG], smz[MAXSEG];
    __shared__ float qred[8];
    __shared__ float s_qmean;

    if (t == 0) {
        // lower_bound(batch, b) and lower_bound(batch, b+1)
        int lo = 0, hi = N;
        while (lo < hi) { int mid = (lo + hi) >> 1; if (batch[mid] < b) lo = mid + 1; else hi = mid; }
        s_s = lo;
        hi = N;
        while (lo < hi) { int mid = (lo + hi) >> 1; if (batch[mid] < b + 1) lo = mid + 1; else hi = mid; }
        s_e = lo;
    }
    __syncthreads();

    int s = s_s, e = s_e;
    int m = e - s;
    if (m > MAXSEG) m = MAXSEG;

    float part = 0.0f;
    if (m > 0) {
        for (int k = t; k < m; k += 256) {
            int i = s + k;
            sx[k] = pos[i * 3 + 0];
            sy[k] = pos[i * 3 + 1];
            sz[k] = pos[i * 3 + 2];
            sq[k] = g_q[i];
            sc[k] = g_sc6[i];
            smx[k] = g_mu[i * 3 + 0];
            smy[k] = g_mu[i * 3 + 1];
            smz[k] = g_mu[i * 3 + 2];
        }
        __syncthreads();

        // q mean over the segment
        float ls = 0.0f;
        for (int k = t; k < m; k += 256) ls += sq[k];
        #pragma unroll
        for (int off = 16; off >= 1; off >>= 1)
            ls += __shfl_xor_sync(0xffffffffu, ls, off);
        if ((t & 31) == 0) qred[t >> 5] = ls;
        __syncthreads();
        if (t == 0) {
            float tot = 0.0f;
            #pragma unroll
            for (int w = 0; w < 8; w++) tot += qred[w];
            s_qmean = tot / (float)m;
        }
        __syncthreads();
        float qmean = s_qmean;
        for (int k = t; k < m; k += 256) sq[k] -= qmean;
        __syncthreads();

        int total = m * m;
        for (int p = slice * 256 + t; p < total; p += SPLIT * 256) {
            int i = p / m;
            int j = p - i * m;
            if (j <= i) continue;      // symmetric terms -> unordered pairs, no 0.5

            float dx = sx[i] - sx[j];
            float dy = sy[i] - sy[j];
            float dz = sz[i] - sz[j];
            float d2 = dx * dx + dy * dy + dz * dz;
            float dist = sqrtf(d2 + 1e-8f);

            // Coulomb
            float f_taper = 1.0f - __expf(-0.5f * dist);
            float ec = __fdividef(sq[i] * sq[j], dist) * f_taper;

            // vdW
            float r6 = d2 * d2 * d2;
            float ev = -__fdividef(sc[i] * sc[j], r6 + 20.0f);

            // dipole-dipole
            float mm  = smx[i] * smx[j] + smy[i] * smy[j] + smz[i] * smz[j];
            float mdi = smx[i] * dx + smy[i] * dy + smz[i] * dz;
            float mdj = smx[j] * dx + smy[j] * dy + smz[j] * dz;
            float invn = __fdividef(1.0f, dist + 1e-8f);
            float ed = __fdividef(mm - 3.0f * mdi * mdj * invn * invn, d2 * dist + 10.0f);

            part += ec * 14.399f + ev + ed;
        }
    }

    // block reduce
    __shared__ float rbuf[256];
    rbuf[t] = part;
    __syncthreads();
    #pragma unroll
    for (int off = 128; off >= 1; off >>= 1) {
        if (t < off) rbuf[t] += rbuf[t + off];
        __syncthreads();
    }

    if (t == 0) {
        atomicAdd(&g_energy, (double)rbuf[0]);
        __threadfence();
        int done = atomicAdd(&g_done, 1);
        if (done == (int)gridDim.x - 1)
            out[0] = (float)g_energy;
    }
}

// ---------------- launch ----------------
extern "C" void kernel_launch(void* const* d_in, const int* in_sizes, int n_in,
                              void* d_out, int out_size)
{
    const float* h0    = (const float*)d_in[0];
    const float* h1    = (const float*)d_in[1];
    const float* pos   = (const float*)d_in[2];
    const int*   batch = (const int*)  d_in[3];
    const float* qW1   = (const float*)d_in[4];
    const float* qb1   = (const float*)d_in[5];
    const float* qW2   = (const float*)d_in[6];
    const float* qb2   = (const float*)d_in[7];
    const float* cW1   = (const float*)d_in[8];
    const float* cb1   = (const float*)d_in[9];
    const float* cW2   = (const float*)d_in[10];
    const float* cb2   = (const float*)d_in[11];
    const float* muW   = (const float*)d_in[12];

    int N = in_sizes[3];

    features_kernel<<<N / TA, 256>>>(h0, h1, qW1, qb1, qW2, qb2,
                                     cW1, cb1, cW2, cb2, muW);
    pair_kernel<<<NB * SPLIT, 256>>>(pos, batch, (float*)d_out, N);
}

// round 3
// speedup vs baseline: 2.0744x; 2.0379x over previous
#include <cuda_runtime.h>
#include <cuda_bf16.h>
#include <math.h>

#define MAXN   8192
#define FDIM   128
#define HDIM   64
#define NB     48
#define TA     8         // atoms per feature block
#define MAXSEG 320       // max atoms per molecule (mean 128, sd ~11)
#define SPLIT  16        // blocks per molecule in pair kernel

// ---------------- device scratch ----------------
__device__ double g_energy;
__device__ int    g_done;
__device__ float  g_q[MAXN];
__device__ float  g_sc6[MAXN];      // sqrt(softplus(c6_raw))
__device__ float  g_mu[MAXN * 3];
__device__ int    g_start[NB];
__device__ int    g_end[NB];

// ================= features: q, sqrt(softplus(c6)), mu, segment bounds ======
// 128 threads, 8 atoms per block. Thread t: hidden unit t&63 of MLP t>>6.
__global__ __launch_bounds__(128) void features_kernel(
    const float* __restrict__ h0, const float* __restrict__ h1,
    const int*   __restrict__ batch,
    const float* __restrict__ qW1, const float* __restrict__ qb1,
    const float* __restrict__ qW2, const float* __restrict__ qb2,
    const float* __restrict__ cW1, const float* __restrict__ cb1,
    const float* __restrict__ cW2, const float* __restrict__ cb2,
    const float* __restrict__ muW, int N)
{
    int t  = threadIdx.x;          // 0..127
    int a0 = blockIdx.x * TA;

    if (blockIdx.x == 0 && t == 0) { g_energy = 0.0; g_done = 0; }

    __shared__ float h0s[TA][FDIM];    // 4 KB
    __shared__ float part[4][TA];      // per-warp partials

    // stage h0 tile: 8*128 = 1024 floats = 256 float4, 128 threads -> 2 each
    {
        const float4* src = (const float4*)(h0 + (size_t)a0 * FDIM);
        float4* dst = (float4*)&h0s[0][0];
        dst[t]       = src[t];
        dst[t + 128] = src[t + 128];
    }

    // segment boundary detection (batch is sorted)
    if (t < TA) {
        int i  = a0 + t;
        int bi = batch[i];
        if (i == 0 || batch[i - 1] != bi) g_start[bi] = i;
        if (i == N - 1 || batch[i + 1] != bi) g_end[bi] = i + 1;
    }
    __syncthreads();

    int mlp = t >> 6;          // 0 = q, 1 = c
    int hu  = t & 63;
    const float* W1 = mlp ? cW1 : qW1;
    const float* B1 = mlp ? cb1 : qb1;
    const float* W2 = mlp ? cW2 : qW2;

    float acc[TA];
    #pragma unroll
    for (int a = 0; a < TA; a++) acc[a] = 0.0f;

    #pragma unroll 4
    for (int f0 = 0; f0 < FDIM; f0 += 4) {
        float w0 = W1[(f0 + 0) * HDIM + hu];
        float w1 = W1[(f0 + 1) * HDIM + hu];
        float w2 = W1[(f0 + 2) * HDIM + hu];
        float w3 = W1[(f0 + 3) * HDIM + hu];
        #pragma unroll
        for (int a = 0; a < TA; a++) {
            float4 h = *(const float4*)&h0s[a][f0];   // broadcast within warp
            acc[a] = fmaf(h.x, w0, acc[a]);
            acc[a] = fmaf(h.y, w1, acc[a]);
            acc[a] = fmaf(h.z, w2, acc[a]);
            acc[a] = fmaf(h.w, w3, acc[a]);
        }
    }

    float b1v = B1[hu];
    float w2v = W2[hu];
    int warp = t >> 5, lane = t & 31;

    #pragma unroll
    for (int a = 0; a < TA; a++) {
        float pre = acc[a] + b1v;
        float v   = (pre / (1.0f + __expf(-pre))) * w2v;   // silu * W2
        #pragma unroll
        for (int off = 16; off >= 1; off >>= 1)
            v += __shfl_xor_sync(0xffffffffu, v, off);
        if (lane == 0) part[warp][a] = v;
    }
    __syncthreads();

    if (t < 2 * TA) {
        int m2 = t >> 3, a = t & 7;    // m2: 0=q, 1=c
        float sum = part[2 * m2][a] + part[2 * m2 + 1][a];
        if (m2 == 0) {
            g_q[a0 + a] = sum + qb2[0];
        } else {
            float c_raw = sum + cb2[0];
            float sp = (c_raw > 20.0f) ? c_raw : log1pf(__expf(c_raw));
            g_sc6[a0 + a] = sqrtf(sp);
        }
    }

    // mu[d] = h1[atom,d,:] . muW  -- 24 rows, 4 warps -> 6 rows each
    float mw0 = muW[lane], mw1 = muW[lane + 32];
    float mw2 = muW[lane + 64], mw3 = muW[lane + 96];
    for (int r = warp; r < 3 * TA; r += 4) {
        int atom = a0 + r / 3, d = r % 3;
        const float* row = h1 + ((size_t)atom * 3 + d) * FDIM;
        float v = row[lane] * mw0 + row[lane + 32] * mw1
                + row[lane + 64] * mw2 + row[lane + 96] * mw3;
        #pragma unroll
        for (int off = 16; off >= 1; off >>= 1)
            v += __shfl_xor_sync(0xffffffffu, v, off);
        if (lane == 0) g_mu[atom * 3 + d] = v;
    }
}

// ================= pairwise energy ==========================================
// 128 threads. SPLIT blocks per molecule; warp owns rows i (boustrophedon),
// lanes stride over j > i.
__global__ __launch_bounds__(128) void pair_kernel(
    const float* __restrict__ pos, float* __restrict__ out)
{
    int b     = blockIdx.x / SPLIT;
    int slice = blockIdx.x % SPLIT;
    int t     = threadIdx.x;
    int warp  = t >> 5, lane = t & 31;

    __shared__ float sx[MAXSEG], sy[MAXSEG], sz[MAXSEG];
    __shared__ float sq[MAXSEG], sc[MAXSEG];
    __shared__ float smx[MAXSEG], smy[MAXSEG], smz[MAXSEG];
    __shared__ float qred[4];
    __shared__ float s_qmean;
    __shared__ float ered[4];

    int s = g_start[b];
    int e = g_end[b];
    int m = e - s;
    if (m > MAXSEG) m = MAXSEG;

    float accE = 0.0f;
    if (m > 0) {
        for (int k = t; k < m; k += 128) {
            int i = s + k;
            sx[k] = pos[i * 3 + 0];
            sy[k] = pos[i * 3 + 1];
            sz[k] = pos[i * 3 + 2];
            sq[k] = g_q[i];
            sc[k] = g_sc6[i];
            smx[k] = g_mu[i * 3 + 0];
            smy[k] = g_mu[i * 3 + 1];
            smz[k] = g_mu[i * 3 + 2];
        }
        __syncthreads();

        // q mean over segment
        float ls = 0.0f;
        for (int k = t; k < m; k += 128) ls += sq[k];
        #pragma unroll
        for (int off = 16; off >= 1; off >>= 1)
            ls += __shfl_xor_sync(0xffffffffu, ls, off);
        if (lane == 0) qred[warp] = ls;
        __syncthreads();
        if (t == 0)
            s_qmean = (qred[0] + qred[1] + qred[2] + qred[3]) / (float)m;
        __syncthreads();
        float qmean = s_qmean;
        for (int k = t; k < m; k += 128) sq[k] -= qmean;
        __syncthreads();

        const int W  = SPLIT * 4;            // warps per molecule
        int wm = slice * 4 + warp;

        for (int k = 0; k * W < m; k++) {
            int i = (k & 1) ? ((k + 1) * W - 1 - wm) : (k * W + wm);
            if (i >= m - 1) continue;
            float xi = sx[i], yi = sy[i], zi = sz[i];
            float qi = sq[i] * 14.399f, ci = sc[i];
            float mxi = smx[i], myi = smy[i], mzi = smz[i];

            for (int j = i + 1 + lane; j < m; j += 32) {
                float dx = xi - sx[j];
                float dy = yi - sy[j];
                float dz = zi - sz[j];
                float d2 = fmaf(dx, dx, fmaf(dy, dy, dz * dz));
                float d2e = d2 + 1e-8f;
                float invd = rsqrtf(d2e);
                float dist = d2e * invd;

                // Coulomb (14.399 prefolded into qi)
                float taper = 1.0f - __expf(-0.5f * dist);
                float ev = qi * sq[j] * invd * taper;

                // vdW
                float r6 = d2 * d2 * d2;
                ev -= __fdividef(ci * sc[j], r6 + 20.0f);

                // dipole-dipole
                float mm  = mxi * smx[j] + myi * smy[j] + mzi * smz[j];
                float mdi = mxi * dx + myi * dy + mzi * dz;
                float mdj = smx[j] * dx + smy[j] * dy + smz[j] * dz;
                float num = mm - 3.0f * mdi * mdj * invd * invd;
                ev += __fdividef(num, d2 * dist + 10.0f);

                accE += ev;
            }
        }
    }

    // block reduce
    #pragma unroll
    for (int off = 16; off >= 1; off >>= 1)
        accE += __shfl_xor_sync(0xffffffffu, accE, off);
    if (lane == 0) ered[warp] = accE;
    __syncthreads();

    if (t == 0) {
        atomicAdd(&g_energy, (double)(ered[0] + ered[1] + ered[2] + ered[3]));
        __threadfence();
        int done = atomicAdd(&g_done, 1);
        if (done == (int)gridDim.x - 1)
            out[0] = (float)g_energy;
    }
}

// ---------------- launch ----------------
extern "C" void kernel_launch(void* const* d_in, const int* in_sizes, int n_in,
                              void* d_out, int out_size)
{
    const float* h0    = (const float*)d_in[0];
    const float* h1    = (const float*)d_in[1];
    const float* pos   = (const float*)d_in[2];
    const int*   batch = (const int*)  d_in[3];
    const float* qW1   = (const float*)d_in[4];
    const float* qb1   = (const float*)d_in[5];
    const float* qW2   = (const float*)d_in[6];
    const float* qb2   = (const float*)d_in[7];
    const float* cW1   = (const float*)d_in[8];
    const float* cb1   = (const float*)d_in[9];
    const float* cW2   = (const float*)d_in[10];
    const float* cb2   = (const float*)d_in[11];
    const float* muW   = (const float*)d_in[12];

    int N = in_sizes[3];

    features_kernel<<<N / TA, 128>>>(h0, h1, batch, qW1, qb1, qW2, qb2,
                                     cW1, cb1, cW2, cb2, muW, N);
    pair_kernel<<<NB * SPLIT, 128>>>(pos, (float*)d_out);
}